// round 8
// baseline (speedup 1.0000x reference)
#include <cuda_runtime.h>
#include <math.h>
#include <stdint.h>

#define H 2048
#define NH 16
#define HD 128
#define SEQ 2048
#define BATCH 2
#define NQKV (H + 2*HD)   // 2304
#define SCALE 0.08838834764831843f  // 1/sqrt(128)

// Scratch (allocation-free rule: __device__ globals)
__device__ float g_qkv[(size_t)BATCH * SEQ * NQKV];   // ~37.7 MB
__device__ float g_attn[(size_t)BATCH * SEQ * H];     // ~33.5 MB

__device__ __forceinline__ uint32_t f2tf32(float x) {
    uint32_t r;
    asm("cvt.rna.tf32.f32 %0, %1;" : "=r"(r) : "f"(x));
    return r;
}
__device__ __forceinline__ void mma8(float* c, uint32_t a0, uint32_t a1,
                                     uint32_t a2, uint32_t a3,
                                     uint32_t b0, uint32_t b1) {
    asm volatile(
        "mma.sync.aligned.m16n8k8.row.col.f32.tf32.tf32.f32 "
        "{%0,%1,%2,%3}, {%4,%5,%6,%7}, {%8,%9}, {%0,%1,%2,%3};"
        : "+f"(c[0]), "+f"(c[1]), "+f"(c[2]), "+f"(c[3])
        : "r"(a0), "r"(a1), "r"(a2), "r"(a3), "r"(b0), "r"(b1));
}

// Fast exp on the FMA pipe (avoids the MUFU throughput floor). x <= 0.
__device__ __forceinline__ float fast_exp(float x) {
    float t = fmaxf(x * 1.4426950408889634f, -126.0f);
    float fl = floorf(t);
    float f = t - fl;
    float p =              1.535336188319500e-4f;
    p = fmaf(p, f, 1.339887440266574e-3f);
    p = fmaf(p, f, 9.618437357674640e-3f);
    p = fmaf(p, f, 5.550332471162809e-2f);
    p = fmaf(p, f, 2.402264791363012e-1f);
    p = fmaf(p, f, 6.931472028550421e-1f);
    p = fmaf(p, f, 1.0f);
    uint32_t sc = ((uint32_t)(int)(fl + 127.0f)) << 23;
    return p * __uint_as_float(sc);
}

// ---------------------------------------------------------------------------
// TF32 tensor-core GEMM with bias (stable at ~246/217us).
// ---------------------------------------------------------------------------
template<int N>
__global__ void __launch_bounds__(256) gemm_tf32(
    const float* __restrict__ A, const float* __restrict__ B,
    const float* __restrict__ bias, float* __restrict__ C, int K)
{
    __shared__ uint32_t As[128][36];
    __shared__ uint32_t Bs[32][136];

    const int tid  = threadIdx.x;
    const int warp = tid >> 5, lane = tid & 31;
    const int wm = warp >> 2, wn = warp & 3;
    const int g  = lane >> 2, tg = lane & 3;
    const int m0 = blockIdx.y * 128;
    const int n0 = blockIdx.x * 128;

    const int ar  = tid >> 3;
    const int ac4 = (tid & 7) * 4;
    const int bc4 = (tid & 31) * 4;
    const int br  = tid >> 5;

    float acc[4][4][4];
    #pragma unroll
    for (int i = 0; i < 4; i++)
        #pragma unroll
        for (int j = 0; j < 4; j++)
            #pragma unroll
            for (int c = 0; c < 4; c++) acc[i][j][c] = 0.f;

    for (int kt = 0; kt < K; kt += 32) {
        __syncthreads();
        #pragma unroll
        for (int i = 0; i < 4; i++) {
            float4 v = *(const float4*)(A + (size_t)(m0 + ar + 32*i) * K + kt + ac4);
            uint4 t = {f2tf32(v.x), f2tf32(v.y), f2tf32(v.z), f2tf32(v.w)};
            *(uint4*)&As[ar + 32*i][ac4] = t;
        }
        #pragma unroll
        for (int i = 0; i < 4; i++) {
            float4 v = *(const float4*)(B + (size_t)(kt + br + 8*i) * N + n0 + bc4);
            uint4 t = {f2tf32(v.x), f2tf32(v.y), f2tf32(v.z), f2tf32(v.w)};
            *(uint4*)&Bs[br + 8*i][bc4] = t;
        }
        __syncthreads();

        #pragma unroll
        for (int ks = 0; ks < 4; ks++) {
            const int kb = ks * 8;
            uint32_t a[4][4], b[4][2];
            #pragma unroll
            for (int mt = 0; mt < 4; mt++) {
                const int mb = wm * 64 + mt * 16;
                a[mt][0] = As[mb + g    ][kb + tg    ];
                a[mt][1] = As[mb + g + 8][kb + tg    ];
                a[mt][2] = As[mb + g    ][kb + tg + 4];
                a[mt][3] = As[mb + g + 8][kb + tg + 4];
            }
            #pragma unroll
            for (int nt = 0; nt < 4; nt++) {
                const int nb = wn * 32 + nt * 8;
                b[nt][0] = Bs[kb + tg    ][nb + g];
                b[nt][1] = Bs[kb + tg + 4][nb + g];
            }
            #pragma unroll
            for (int mt = 0; mt < 4; mt++)
                #pragma unroll
                for (int nt = 0; nt < 4; nt++)
                    mma8(acc[mt][nt], a[mt][0], a[mt][1], a[mt][2], a[mt][3],
                         b[nt][0], b[nt][1]);
        }
    }

    #pragma unroll
    for (int nt = 0; nt < 4; nt++) {
        const int col = n0 + wn * 32 + nt * 8 + 2 * tg;
        float2 bv = *(const float2*)(bias + col);
        #pragma unroll
        for (int mt = 0; mt < 4; mt++) {
            const int row0 = m0 + wm * 64 + mt * 16 + g;
            float2 r0 = {acc[mt][nt][0] + bv.x, acc[mt][nt][1] + bv.y};
            float2 r1 = {acc[mt][nt][2] + bv.x, acc[mt][nt][3] + bv.y};
            *(float2*)(C + (size_t)row0 * N + col)       = r0;
            *(float2*)(C + (size_t)(row0 + 8) * N + col) = r1;
        }
    }
}

// ---------------------------------------------------------------------------
// Causal MQA flash attention, FlashAttention-2 style warp ownership:
// 8 warps x 16 q-rows each, full BK=64 per warp -> softmax fully in
// registers (quad shfl), P transposed to a-frags via quad shuffles,
// single-pass tf32 mma throughout. 2 barriers/tile, no S/P/m/l smem.
// Smem strides (u32): Q/K 132 (==4 mod 32), V 136 (==8 mod 32):
// all fragment-load lane patterns cover 32 banks exactly once.
// ---------------------------------------------------------------------------
#define PQ 132
#define PV 136
#define OFF_Q 0
#define OFF_K (OFF_Q + 128*PQ)
#define OFF_V (OFF_K + 64*PQ)
#define ATTN_U32 (OFF_V + 64*PV)
#define ATTN_SMEM_BYTES (ATTN_U32 * 4)    // 136,192 B

__global__ void __launch_bounds__(256) mqa_attn_fa2(
    const float* __restrict__ qkv, float* __restrict__ out)
{
    extern __shared__ uint32_t smem_u[];
    uint32_t* Qs = smem_u + OFF_Q;
    uint32_t* Ks = smem_u + OFF_K;
    uint32_t* Vs = smem_u + OFF_V;

    const int tid  = threadIdx.x;
    const int warp = tid >> 5, lane = tid & 31;
    const int g = lane >> 2, tg = lane & 3;
    const int qt = gridDim.x - 1 - blockIdx.x;   // heavy blocks first
    const int h = blockIdx.y, b = blockIdx.z;
    const int q0 = qt * 128;
    const int r0 = 16 * warp + g;        // warp-local row (lane rows r0, r0+8)

    const float* qbase = qkv + (size_t)b * SEQ * NQKV + h * HD;
    const float* kbase = qkv + (size_t)b * SEQ * NQKV + H;
    const float* vbase = kbase + HD;

    // Load Q tile (128 x 128) once, converted to tf32
    for (int i = tid; i < 128 * 32; i += 256) {
        int r = i >> 5, c4 = (i & 31) * 4;
        float4 v = *(const float4*)(qbase + (size_t)(q0 + r) * NQKV + c4);
        Qs[r*PQ + c4    ] = f2tf32(v.x);
        Qs[r*PQ + c4 + 1] = f2tf32(v.y);
        Qs[r*PQ + c4 + 2] = f2tf32(v.z);
        Qs[r*PQ + c4 + 3] = f2tf32(v.w);
    }

    float o[16][4];
    #pragma unroll
    for (int nt = 0; nt < 16; nt++)
        #pragma unroll
        for (int c = 0; c < 4; c++) o[nt][c] = 0.f;
    float m0 = -1e30f, m1 = -1e30f, l0 = 0.f, l1 = 0.f;

    // shuffle-transpose source lanes (intra-quad permutation)
    const int srcA = (lane & ~3) | (tg >> 1);
    const int srcB = srcA + 2;
    const bool odd = (tg & 1) != 0;

    const int nkt = 2 * qt + 2;
    for (int kt = 0; kt < nkt; kt++) {
        const int k0 = kt * 64;
        __syncthreads();   // prior-iteration readers of K/V done
        for (int i = tid; i < 64 * 32; i += 256) {
            int r = i >> 5, c4 = (i & 31) * 4;
            float4 kv = *(const float4*)(kbase + (size_t)(k0 + r) * NQKV + c4);
            float4 vv = *(const float4*)(vbase + (size_t)(k0 + r) * NQKV + c4);
            Ks[r*PQ + c4    ] = f2tf32(kv.x);
            Ks[r*PQ + c4 + 1] = f2tf32(kv.y);
            Ks[r*PQ + c4 + 2] = f2tf32(kv.z);
            Ks[r*PQ + c4 + 3] = f2tf32(kv.w);
            Vs[r*PV + c4    ] = f2tf32(vv.x);
            Vs[r*PV + c4 + 1] = f2tf32(vv.y);
            Vs[r*PV + c4 + 2] = f2tf32(vv.z);
            Vs[r*PV + c4 + 3] = f2tf32(vv.w);
        }
        __syncthreads();

        // ---- S = Q @ K^T: warp tile 16 x 64, 16 k8-steps ----
        float sacc[8][4];
        #pragma unroll
        for (int nt = 0; nt < 8; nt++)
            #pragma unroll
            for (int c = 0; c < 4; c++) sacc[nt][c] = 0.f;

        #pragma unroll
        for (int ks = 0; ks < 16; ks++) {
            const int kb = ks * 8;
            uint32_t a0 = Qs[(r0    )*PQ + kb + tg    ];
            uint32_t a1 = Qs[(r0 + 8)*PQ + kb + tg    ];
            uint32_t a2 = Qs[(r0    )*PQ + kb + tg + 4];
            uint32_t a3 = Qs[(r0 + 8)*PQ + kb + tg + 4];
            #pragma unroll
            for (int nt = 0; nt < 8; nt++) {
                uint32_t b0 = Ks[(nt*8 + g)*PQ + kb + tg    ];
                uint32_t b1 = Ks[(nt*8 + g)*PQ + kb + tg + 4];
                mma8(sacc[nt], a0, a1, a2, a3, b0, b1);
            }
        }

        // ---- scale + (conditional) causal mask + in-register row stats ----
        const bool need_mask = (k0 + 63 > q0 + 16 * warp);
        float mx0 = -1e30f, mx1 = -1e30f;
        #pragma unroll
        for (int nt = 0; nt < 8; nt++) {
            float s0 = sacc[nt][0] * SCALE;
            float s1 = sacc[nt][1] * SCALE;
            float s2 = sacc[nt][2] * SCALE;
            float s3 = sacc[nt][3] * SCALE;
            if (need_mask) {
                const int c0 = k0 + nt * 8 + 2 * tg, c1 = c0 + 1;
                const int rr0 = q0 + r0, rr1 = rr0 + 8;
                if (c0 > rr0) s0 = -1e30f;
                if (c1 > rr0) s1 = -1e30f;
                if (c0 > rr1) s2 = -1e30f;
                if (c1 > rr1) s3 = -1e30f;
            }
            sacc[nt][0] = s0; sacc[nt][1] = s1;
            sacc[nt][2] = s2; sacc[nt][3] = s3;
            mx0 = fmaxf(mx0, fmaxf(s0, s1));
            mx1 = fmaxf(mx1, fmaxf(s2, s3));
        }
        mx0 = fmaxf(mx0, __shfl_xor_sync(0xffffffffu, mx0, 1));
        mx0 = fmaxf(mx0, __shfl_xor_sync(0xffffffffu, mx0, 2));
        mx1 = fmaxf(mx1, __shfl_xor_sync(0xffffffffu, mx1, 1));
        mx1 = fmaxf(mx1, __shfl_xor_sync(0xffffffffu, mx1, 2));
        const float mn0 = fmaxf(m0, mx0), mn1 = fmaxf(m1, mx1);
        const float f0 = fast_exp(m0 - mn0), f1 = fast_exp(m1 - mn1);
        m0 = mn0; m1 = mn1;

        float sum0 = 0.f, sum1 = 0.f;
        uint32_t pt[8][4];
        #pragma unroll
        for (int nt = 0; nt < 8; nt++) {
            float p0 = fast_exp(sacc[nt][0] - mn0);
            float p1 = fast_exp(sacc[nt][1] - mn0);
            float p2 = fast_exp(sacc[nt][2] - mn1);
            float p3 = fast_exp(sacc[nt][3] - mn1);
            sum0 += p0 + p1;
            sum1 += p2 + p3;
            pt[nt][0] = f2tf32(p0); pt[nt][1] = f2tf32(p1);
            pt[nt][2] = f2tf32(p2); pt[nt][3] = f2tf32(p3);
        }
        sum0 += __shfl_xor_sync(0xffffffffu, sum0, 1);
        sum0 += __shfl_xor_sync(0xffffffffu, sum0, 2);
        sum1 += __shfl_xor_sync(0xffffffffu, sum1, 1);
        sum1 += __shfl_xor_sync(0xffffffffu, sum1, 2);
        l0 = l0 * f0 + sum0;
        l1 = l1 * f1 + sum1;

        // rescale running O
        #pragma unroll
        for (int nt = 0; nt < 16; nt++) {
            o[nt][0] *= f0;  o[nt][1] *= f0;
            o[nt][2] *= f1;  o[nt][3] *= f1;
        }

        // ---- O += P @ V: warp tile 16 x 128, 8 k8-steps ----
        // P a-frags produced by quad shuffle-transpose of accumulator layout.
        #pragma unroll
        for (int ks = 0; ks < 8; ks++) {
            uint32_t x0 = __shfl_sync(0xffffffffu, pt[ks][0], srcA);
            uint32_t x1 = __shfl_sync(0xffffffffu, pt[ks][1], srcA);
            uint32_t x2 = __shfl_sync(0xffffffffu, pt[ks][2], srcA);
            uint32_t x3 = __shfl_sync(0xffffffffu, pt[ks][3], srcA);
            uint32_t y0 = __shfl_sync(0xffffffffu, pt[ks][0], srcB);
            uint32_t y1 = __shfl_sync(0xffffffffu, pt[ks][1], srcB);
            uint32_t y2 = __shfl_sync(0xffffffffu, pt[ks][2], srcB);
            uint32_t y3 = __shfl_sync(0xffffffffu, pt[ks][3], srcB);
            uint32_t pa0 = odd ? x1 : x0;   // P[r0][kb+tg]
            uint32_t pa1 = odd ? x3 : x2;   // P[r0+8][kb+tg]
            uint32_t pa2 = odd ? y1 : y0;   // P[r0][kb+tg+4]
            uint32_t pa3 = odd ? y3 : y2;   // P[r0+8][kb+tg+4]
            const int kb = ks * 8;
            #pragma unroll
            for (int nt = 0; nt < 16; nt++) {
                uint32_t b0 = Vs[(kb + tg    )*PV + nt*8 + g];
                uint32_t b1 = Vs[(kb + tg + 4)*PV + nt*8 + g];
                mma8(o[nt], pa0, pa1, pa2, pa3, b0, b1);
            }
        }
    }

    // final write: o / l
    const float inv0 = 1.f / l0, inv1 = 1.f / l1;
    const size_t rowA = (size_t)(b * SEQ + q0 + r0) * H + h * HD;
    const size_t rowB = (size_t)(b * SEQ + q0 + r0 + 8) * H + h * HD;
    #pragma unroll
    for (int nt = 0; nt < 16; nt++) {
        const int col = nt * 8 + 2 * tg;
        float2 v0 = {o[nt][0] * inv0, o[nt][1] * inv0};
        float2 v1 = {o[nt][2] * inv1, o[nt][3] * inv1};
        *(float2*)(out + rowA + col) = v0;
        *(float2*)(out + rowB + col) = v1;
    }
}

// ---------------------------------------------------------------------------

extern "C" void kernel_launch(void* const* d_in, const int* in_sizes, int n_in,
                              void* d_out, int out_size)
{
    (void)in_sizes; (void)n_in; (void)out_size;
    const float* x     = (const float*)d_in[0];
    const float* Wqkv  = (const float*)d_in[1];
    const float* bqkv  = (const float*)d_in[2];
    const float* Wproj = (const float*)d_in[3];
    const float* bproj = (const float*)d_in[4];
    float* out = (float*)d_out;

    float *qkv_ptr, *attn_ptr;
    cudaGetSymbolAddress((void**)&qkv_ptr, g_qkv);
    cudaGetSymbolAddress((void**)&attn_ptr, g_attn);

    cudaFuncSetAttribute(mqa_attn_fa2, cudaFuncAttributeMaxDynamicSharedMemorySize,
                         ATTN_SMEM_BYTES);

    // 1) QKV GEMM (TF32 tensor cores)
    gemm_tf32<NQKV><<<dim3(NQKV / 128, (BATCH * SEQ) / 128), 256>>>(
        x, Wqkv, bqkv, qkv_ptr, H);

    // 2) causal MQA flash attention (FA2-style, register softmax)
    mqa_attn_fa2<<<dim3(SEQ / 128, NH, BATCH), 256, ATTN_SMEM_BYTES>>>(qkv_ptr, attn_ptr);

    // 3) proj GEMM (TF32 tensor cores)
    gemm_tf32<H><<<dim3(H / 128, (BATCH * SEQ) / 128), 256>>>(
        attn_ptr, Wproj, bproj, out, H);
}

// round 9
// speedup vs baseline: 1.1249x; 1.1249x over previous
#include <cuda_runtime.h>
#include <math.h>
#include <stdint.h>

#define H 2048
#define NH 16
#define HD 128
#define SEQ 2048
#define BATCH 2
#define NQKV (H + 2*HD)   // 2304
#define SCALE 0.08838834764831843f  // 1/sqrt(128)

// Scratch (allocation-free rule: __device__ globals)
__device__ float g_qkv[(size_t)BATCH * SEQ * NQKV];   // ~37.7 MB
__device__ float g_attn[(size_t)BATCH * SEQ * H];     // ~33.5 MB

__device__ __forceinline__ uint32_t f2tf32(float x) {
    uint32_t r;
    asm("cvt.rna.tf32.f32 %0, %1;" : "=r"(r) : "f"(x));
    return r;
}
__device__ __forceinline__ void mma8(float* c, uint32_t a0, uint32_t a1,
                                     uint32_t a2, uint32_t a3,
                                     uint32_t b0, uint32_t b1) {
    asm volatile(
        "mma.sync.aligned.m16n8k8.row.col.f32.tf32.tf32.f32 "
        "{%0,%1,%2,%3}, {%4,%5,%6,%7}, {%8,%9}, {%0,%1,%2,%3};"
        : "+f"(c[0]), "+f"(c[1]), "+f"(c[2]), "+f"(c[3])
        : "r"(a0), "r"(a1), "r"(a2), "r"(a3), "r"(b0), "r"(b1));
}
// ldmatrix x4: loads tf32 fragments (8x4 b32 tile == 8x8 b16 tile, same lane map)
__device__ __forceinline__ void ldsm4(uint32_t* r, uint32_t addr) {
    asm volatile("ldmatrix.sync.aligned.m8n8.x4.shared.b16 {%0,%1,%2,%3}, [%4];"
        : "=r"(r[0]), "=r"(r[1]), "=r"(r[2]), "=r"(r[3]) : "r"(addr));
}
__device__ __forceinline__ uint32_t sm_addr(const void* p) {
    return (uint32_t)__cvta_generic_to_shared(p);
}

// Fast exp on the FMA pipe (avoids the MUFU throughput floor). x <= 0.
__device__ __forceinline__ float fast_exp(float x) {
    float t = fmaxf(x * 1.4426950408889634f, -126.0f);
    float fl = floorf(t);
    float f = t - fl;
    float p =              1.535336188319500e-4f;
    p = fmaf(p, f, 1.339887440266574e-3f);
    p = fmaf(p, f, 9.618437357674640e-3f);
    p = fmaf(p, f, 5.550332471162809e-2f);
    p = fmaf(p, f, 2.402264791363012e-1f);
    p = fmaf(p, f, 6.931472028550421e-1f);
    p = fmaf(p, f, 1.0f);
    uint32_t sc = ((uint32_t)(int)(fl + 127.0f)) << 23;
    return p * __uint_as_float(sc);
}

// ---------------------------------------------------------------------------
// TF32 tensor-core GEMM with bias. A tile row-major [m][k] (stride 36 ==
// 4 mod 32 -> LDSM phases conflict-free), a-frags via ldmatrix.x4.
// ---------------------------------------------------------------------------
template<int N>
__global__ void __launch_bounds__(256) gemm_tf32(
    const float* __restrict__ A, const float* __restrict__ B,
    const float* __restrict__ bias, float* __restrict__ C, int K)
{
    __shared__ uint32_t As[128][36];
    __shared__ uint32_t Bs[32][136];

    const int tid  = threadIdx.x;
    const int warp = tid >> 5, lane = tid & 31;
    const int wm = warp >> 2, wn = warp & 3;
    const int g  = lane >> 2, tg = lane & 3;
    const int m0 = blockIdx.y * 128;
    const int n0 = blockIdx.x * 128;

    const int ar  = tid >> 3;
    const int ac4 = (tid & 7) * 4;
    const int bc4 = (tid & 31) * 4;
    const int br  = tid >> 5;

    // ldmatrix a-frag lane addressing: lane -> row mb + (lane&15), col half
    const int l15 = lane & 15;
    const int ahalf = (lane >> 4) * 4;
    uint32_t aA[4];
    #pragma unroll
    for (int mt = 0; mt < 4; mt++)
        aA[mt] = sm_addr(&As[wm * 64 + mt * 16 + l15][ahalf]);

    float acc[4][4][4];
    #pragma unroll
    for (int i = 0; i < 4; i++)
        #pragma unroll
        for (int j = 0; j < 4; j++)
            #pragma unroll
            for (int c = 0; c < 4; c++) acc[i][j][c] = 0.f;

    for (int kt = 0; kt < K; kt += 32) {
        __syncthreads();
        #pragma unroll
        for (int i = 0; i < 4; i++) {
            float4 v = *(const float4*)(A + (size_t)(m0 + ar + 32*i) * K + kt + ac4);
            uint4 t = {f2tf32(v.x), f2tf32(v.y), f2tf32(v.z), f2tf32(v.w)};
            *(uint4*)&As[ar + 32*i][ac4] = t;    // row-major, direct STS.128
        }
        #pragma unroll
        for (int i = 0; i < 4; i++) {
            float4 v = *(const float4*)(B + (size_t)(kt + br + 8*i) * N + n0 + bc4);
            uint4 t = {f2tf32(v.x), f2tf32(v.y), f2tf32(v.z), f2tf32(v.w)};
            *(uint4*)&Bs[br + 8*i][bc4] = t;
        }
        __syncthreads();

        #pragma unroll
        for (int ks = 0; ks < 4; ks++) {
            const int kb = ks * 8;
            uint32_t a[4][4], b[4][2];
            #pragma unroll
            for (int mt = 0; mt < 4; mt++)
                ldsm4(a[mt], aA[mt] + ks * 32);
            #pragma unroll
            for (int nt = 0; nt < 4; nt++) {
                const int nb = wn * 32 + nt * 8;
                b[nt][0] = Bs[kb + tg    ][nb + g];
                b[nt][1] = Bs[kb + tg + 4][nb + g];
            }
            #pragma unroll
            for (int mt = 0; mt < 4; mt++)
                #pragma unroll
                for (int nt = 0; nt < 4; nt++)
                    mma8(acc[mt][nt], a[mt][0], a[mt][1], a[mt][2], a[mt][3],
                         b[nt][0], b[nt][1]);
        }
    }

    #pragma unroll
    for (int nt = 0; nt < 4; nt++) {
        const int col = n0 + wn * 32 + nt * 8 + 2 * tg;
        float2 bv = *(const float2*)(bias + col);
        #pragma unroll
        for (int mt = 0; mt < 4; mt++) {
            const int row0 = m0 + wm * 64 + mt * 16 + g;
            float2 r0 = {acc[mt][nt][0] + bv.x, acc[mt][nt][1] + bv.y};
            float2 r1 = {acc[mt][nt][2] + bv.x, acc[mt][nt][3] + bv.y};
            *(float2*)(C + (size_t)row0 * N + col)       = r0;
            *(float2*)(C + (size_t)(row0 + 8) * N + col) = r1;
        }
    }
}

// ---------------------------------------------------------------------------
// Causal MQA flash attention: single-pass TF32 m16n8k8, BQ=128 x BK=64,
// 256 threads (warps 4x2). Q/K/P fragment loads via ldmatrix.x4 (strides
// == 4 mod 32 -> conflict-free LDSM phases); V scalar (stride == 8 mod 32).
// ---------------------------------------------------------------------------
#define PQ 132
#define PV 136
#define PS 68

#define OFF_Q 0
#define OFF_K (OFF_Q + 128*PQ)
#define OFF_V (OFF_K + 64*PQ)
#define OFF_S (OFF_V + 64*PV)
#define OFF_M (OFF_S + 128*PS)
#define ATTN_U32 (OFF_M + 3*128)
#define ATTN_SMEM_BYTES (ATTN_U32 * 4)    // 172,544 B

__global__ void __launch_bounds__(256) mqa_attn_tf32(
    const float* __restrict__ qkv, float* __restrict__ out)
{
    extern __shared__ uint32_t smem_u[];
    uint32_t* Qs = smem_u + OFF_Q;
    uint32_t* Ks = smem_u + OFF_K;
    uint32_t* Vs = smem_u + OFF_V;
    float*    Sf = (float*)(smem_u + OFF_S);
    uint32_t* Su = smem_u + OFF_S;           // same buffer as tf32 after softmax
    float* m_s = (float*)(smem_u + OFF_M);
    float* l_s = m_s + 128;
    float* f_s = l_s + 128;

    const int tid  = threadIdx.x;
    const int warp = tid >> 5, lane = tid & 31;
    const int g = lane >> 2, tg = lane & 3;
    const int wm = warp >> 1, wn = warp & 1;     // 4 x 2 warp grid
    const int qt = gridDim.x - 1 - blockIdx.x;   // heavy blocks first
    const int h = blockIdx.y, b = blockIdx.z;
    const int q0 = qt * 128;

    const float* qbase = qkv + (size_t)b * SEQ * NQKV + h * HD;
    const float* kbase = qkv + (size_t)b * SEQ * NQKV + H;
    const float* vbase = kbase + HD;

    // ldmatrix lane addressing
    const int l15 = lane & 15;
    const int ahalf = (lane >> 4) * 4;                       // a-frag col half
    const int brow  = (lane & 7) + ((lane >> 4) & 1) * 8;    // b-frag row
    const int bcol  = ((lane >> 3) & 1) * 4;                 // b-frag col half
    uint32_t qA[2], pA[2], kA[2];
    #pragma unroll
    for (int mt = 0; mt < 2; mt++) {
        const int row = wm * 32 + mt * 16 + l15;
        qA[mt] = sm_addr(Qs + row * PQ + ahalf);
        pA[mt] = sm_addr(Su + row * PS + ahalf);
    }
    #pragma unroll
    for (int p = 0; p < 2; p++)
        kA[p] = sm_addr(Ks + (wn * 32 + p * 16 + brow) * PQ + bcol);

    // Load Q tile (128 x 128) once, converted to tf32
    for (int i = tid; i < 128 * 32; i += 256) {
        int r = i >> 5, c4 = (i & 31) * 4;
        float4 v = *(const float4*)(qbase + (size_t)(q0 + r) * NQKV + c4);
        uint4 t = {f2tf32(v.x), f2tf32(v.y), f2tf32(v.z), f2tf32(v.w)};
        *(uint4*)&Qs[r*PQ + c4] = t;
    }
    if (tid < 128) { m_s[tid] = -1e30f; l_s[tid] = 0.f; }

    float o[2][8][4];
    #pragma unroll
    for (int mt = 0; mt < 2; mt++)
        #pragma unroll
        for (int nt = 0; nt < 8; nt++)
            #pragma unroll
            for (int c = 0; c < 4; c++) o[mt][nt][c] = 0.f;

    const int nkt = 2 * qt + 2;
    for (int kt = 0; kt < nkt; kt++) {
        const int k0 = kt * 64;
        __syncthreads();   // prior-iteration readers of K/V done
        for (int i = tid; i < 64 * 32; i += 256) {
            int r = i >> 5, c4 = (i & 31) * 4;
            float4 kv = *(const float4*)(kbase + (size_t)(k0 + r) * NQKV + c4);
            float4 vv = *(const float4*)(vbase + (size_t)(k0 + r) * NQKV + c4);
            uint4 tk = {f2tf32(kv.x), f2tf32(kv.y), f2tf32(kv.z), f2tf32(kv.w)};
            uint4 tv = {f2tf32(vv.x), f2tf32(vv.y), f2tf32(vv.z), f2tf32(vv.w)};
            *(uint4*)&Ks[r*PQ + c4] = tk;
            *(uint4*)&Vs[r*PV + c4] = tv;
        }
        __syncthreads();

        // ---- S = Q @ K^T (128x64), warp tile 32x32, 16 k8-steps ----
        float sacc[2][4][4];
        #pragma unroll
        for (int mt = 0; mt < 2; mt++)
            #pragma unroll
            for (int nt = 0; nt < 4; nt++)
                #pragma unroll
                for (int c = 0; c < 4; c++) sacc[mt][nt][c] = 0.f;

        #pragma unroll
        for (int ks = 0; ks < 16; ks++) {
            uint32_t a[2][4], b01[4], b23[4];
            ldsm4(a[0], qA[0] + ks * 32);
            ldsm4(a[1], qA[1] + ks * 32);
            ldsm4(b01, kA[0] + ks * 32);   // (b0,b1) for nt0, nt1
            ldsm4(b23, kA[1] + ks * 32);   // (b0,b1) for nt2, nt3
            #pragma unroll
            for (int mt = 0; mt < 2; mt++) {
                mma8(sacc[mt][0], a[mt][0], a[mt][1], a[mt][2], a[mt][3], b01[0], b01[1]);
                mma8(sacc[mt][1], a[mt][0], a[mt][1], a[mt][2], a[mt][3], b01[2], b01[3]);
                mma8(sacc[mt][2], a[mt][0], a[mt][1], a[mt][2], a[mt][3], b23[0], b23[1]);
                mma8(sacc[mt][3], a[mt][0], a[mt][1], a[mt][2], a[mt][3], b23[2], b23[3]);
            }
        }

        // scale + (uniform-branch) causal mask + store S (fp32)
        const bool need_mask = (k0 + 63 > q0 + wm * 32);
        #pragma unroll
        for (int mt = 0; mt < 2; mt++) {
            const int mb = wm * 32 + mt * 16;
            #pragma unroll
            for (int nt = 0; nt < 4; nt++) {
                const int nb = wn * 32 + nt * 8;
                const int c0 = nb + 2 * tg, c1 = c0 + 1;
                const int r0 = mb + g, r1 = mb + g + 8;
                float s00 = sacc[mt][nt][0] * SCALE;
                float s01 = sacc[mt][nt][1] * SCALE;
                float s10 = sacc[mt][nt][2] * SCALE;
                float s11 = sacc[mt][nt][3] * SCALE;
                if (need_mask) {
                    if (k0 + c0 > q0 + r0) s00 = -1e30f;
                    if (k0 + c1 > q0 + r0) s01 = -1e30f;
                    if (k0 + c0 > q0 + r1) s10 = -1e30f;
                    if (k0 + c1 > q0 + r1) s11 = -1e30f;
                }
                Sf[r0*PS + c0] = s00;  Sf[r0*PS + c1] = s01;
                Sf[r1*PS + c0] = s10;  Sf[r1*PS + c1] = s11;
            }
        }
        __syncthreads();

        // ---- online softmax: 2 threads/row; P written back as tf32 ----
        {
            const int row = tid >> 1, sub = tid & 1;
            float* srow = Sf + row*PS + sub*32;
            uint32_t* urow = Su + row*PS + sub*32;
            float mold = m_s[row];
            float mx = mold;
            #pragma unroll
            for (int c = 0; c < 8; c++) {
                float4 t = *(float4*)&srow[4*c];
                mx = fmaxf(mx, fmaxf(fmaxf(t.x, t.y), fmaxf(t.z, t.w)));
            }
            mx = fmaxf(mx, __shfl_xor_sync(0xffffffffu, mx, 1));
            float sum = 0.f;
            #pragma unroll
            for (int j = 0; j < 8; j++) {
                float4 t = *(float4*)&srow[4*j];
                float p0 = fast_exp(t.x - mx), p1 = fast_exp(t.y - mx);
                float p2 = fast_exp(t.z - mx), p3 = fast_exp(t.w - mx);
                sum += (p0 + p1) + (p2 + p3);
                uint4 u = {f2tf32(p0), f2tf32(p1), f2tf32(p2), f2tf32(p3)};
                *(uint4*)&urow[4*j] = u;
            }
            sum += __shfl_xor_sync(0xffffffffu, sum, 1);
            if (sub == 0) {
                float f = fast_exp(mold - mx);
                l_s[row] = l_s[row] * f + sum;
                m_s[row] = mx;
                f_s[row] = f;
            }
        }
        __syncthreads();

        // ---- O = O*f + P @ V (128x128), warp tile 32x64, 8 k8-steps ----
        float fr[2][2];
        #pragma unroll
        for (int mt = 0; mt < 2; mt++) {
            const int mb = wm * 32 + mt * 16;
            fr[mt][0] = f_s[mb + g];
            fr[mt][1] = f_s[mb + g + 8];
        }
        #pragma unroll
        for (int mt = 0; mt < 2; mt++)
            #pragma unroll
            for (int nt = 0; nt < 8; nt++) {
                o[mt][nt][0] *= fr[mt][0];  o[mt][nt][1] *= fr[mt][0];
                o[mt][nt][2] *= fr[mt][1];  o[mt][nt][3] *= fr[mt][1];
            }

        #pragma unroll
        for (int ks = 0; ks < 8; ks++) {
            const int kb = ks * 8;
            uint32_t a[2][4];
            ldsm4(a[0], pA[0] + ks * 32);
            ldsm4(a[1], pA[1] + ks * 32);
            #pragma unroll
            for (int nt = 0; nt < 8; nt++) {
                const int nb = wn * 64 + nt * 8;
                uint32_t b0 = Vs[(kb + tg    )*PV + nb + g];
                uint32_t b1 = Vs[(kb + tg + 4)*PV + nb + g];
                #pragma unroll
                for (int mt = 0; mt < 2; mt++)
                    mma8(o[mt][nt], a[mt][0], a[mt][1], a[mt][2], a[mt][3], b0, b1);
            }
        }
    }

    __syncthreads();
    // final write: o / l
    #pragma unroll
    for (int mt = 0; mt < 2; mt++) {
        const int mb = wm * 32 + mt * 16;
        const float inv0 = 1.f / l_s[mb + g];
        const float inv1 = 1.f / l_s[mb + g + 8];
        #pragma unroll
        for (int nt = 0; nt < 8; nt++) {
            const int col = wn * 64 + nt * 8 + 2 * tg;
            size_t row0 = (size_t)(b * SEQ + q0 + mb + g) * H + h * HD + col;
            size_t row1 = (size_t)(b * SEQ + q0 + mb + g + 8) * H + h * HD + col;
            float2 r0 = {o[mt][nt][0] * inv0, o[mt][nt][1] * inv0};
            float2 r1 = {o[mt][nt][2] * inv1, o[mt][nt][3] * inv1};
            *(float2*)(out + row0) = r0;
            *(float2*)(out + row1) = r1;
        }
    }
}

// ---------------------------------------------------------------------------

extern "C" void kernel_launch(void* const* d_in, const int* in_sizes, int n_in,
                              void* d_out, int out_size)
{
    (void)in_sizes; (void)n_in; (void)out_size;
    const float* x     = (const float*)d_in[0];
    const float* Wqkv  = (const float*)d_in[1];
    const float* bqkv  = (const float*)d_in[2];
    const float* Wproj = (const float*)d_in[3];
    const float* bproj = (const float*)d_in[4];
    float* out = (float*)d_out;

    float *qkv_ptr, *attn_ptr;
    cudaGetSymbolAddress((void**)&qkv_ptr, g_qkv);
    cudaGetSymbolAddress((void**)&attn_ptr, g_attn);

    cudaFuncSetAttribute(mqa_attn_tf32, cudaFuncAttributeMaxDynamicSharedMemorySize,
                         ATTN_SMEM_BYTES);

    // 1) QKV GEMM (TF32 tensor cores + ldmatrix a-frags)
    gemm_tf32<NQKV><<<dim3(NQKV / 128, (BATCH * SEQ) / 128), 256>>>(
        x, Wqkv, bqkv, qkv_ptr, H);

    // 2) causal MQA flash attention (TF32 mma + ldmatrix Q/K/P frags)
    mqa_attn_tf32<<<dim3(SEQ / 128, NH, BATCH), 256, ATTN_SMEM_BYTES>>>(qkv_ptr, attn_ptr);

    // 3) proj GEMM (TF32 tensor cores + ldmatrix a-frags)
    gemm_tf32<H><<<dim3(H / 128, (BATCH * SEQ) / 128), 256>>>(
        attn_ptr, Wproj, bproj, out, H);
}

// round 11
// speedup vs baseline: 1.1402x; 1.0137x over previous
#include <cuda_runtime.h>
#include <math.h>
#include <stdint.h>

#define H 2048
#define NH 16
#define HD 128
#define SEQ 2048
#define BATCH 2
#define NQKV (H + 2*HD)   // 2304
#define SCALE 0.08838834764831843f  // 1/sqrt(128)
#define MROWS (BATCH*SEQ)

// ---------------- global scratch (allocation-free rule) ----------------
__device__ float    g_qkv[(size_t)MROWS * NQKV];   // tf32-rounded qkv
__device__ float    g_attn[(size_t)MROWS * H];     // tf32-rounded attn out
__device__ uint32_t g_xt[(size_t)MROWS * H];       // x, tf32-rounded
__device__ uint32_t g_wqt[(size_t)NQKV * H];       // Wqkv^T [N][K] rounded
__device__ uint32_t g_wpt[(size_t)H * H];          // Wproj^T [N][K] rounded

// ---------------- helpers ----------------
__device__ __forceinline__ uint32_t f2tf32(float x) {
    uint32_t r;
    asm("cvt.rna.tf32.f32 %0, %1;" : "=r"(r) : "f"(x));
    return r;
}
__device__ __forceinline__ void mma8(float* c, uint32_t a0, uint32_t a1,
                                     uint32_t a2, uint32_t a3,
                                     uint32_t b0, uint32_t b1) {
    asm volatile(
        "mma.sync.aligned.m16n8k8.row.col.f32.tf32.tf32.f32 "
        "{%0,%1,%2,%3}, {%4,%5,%6,%7}, {%8,%9}, {%0,%1,%2,%3};"
        : "+f"(c[0]), "+f"(c[1]), "+f"(c[2]), "+f"(c[3])
        : "r"(a0), "r"(a1), "r"(a2), "r"(a3), "r"(b0), "r"(b1));
}
__device__ __forceinline__ void ldsm4(uint32_t* r, uint32_t addr) {
    asm volatile("ldmatrix.sync.aligned.m8n8.x4.shared.b16 {%0,%1,%2,%3}, [%4];"
        : "=r"(r[0]), "=r"(r[1]), "=r"(r[2]), "=r"(r[3]) : "r"(addr));
}
__device__ __forceinline__ uint32_t sm_addr(const void* p) {
    return (uint32_t)__cvta_generic_to_shared(p);
}
__device__ __forceinline__ void cp16(uint32_t dst, const void* src) {
    asm volatile("cp.async.cg.shared.global [%0], [%1], 16;" :: "r"(dst), "l"(src));
}
__device__ __forceinline__ void cp_commit() {
    asm volatile("cp.async.commit_group;");
}
template<int N>
__device__ __forceinline__ void cp_wait() {
    asm volatile("cp.async.wait_group %0;" :: "n"(N));
}
__device__ __forceinline__ float fast_exp(float x) {
    float t = fmaxf(x * 1.4426950408889634f, -126.0f);
    float fl = floorf(t);
    float f = t - fl;
    float p =              1.535336188319500e-4f;
    p = fmaf(p, f, 1.339887440266574e-3f);
    p = fmaf(p, f, 9.618437357674640e-3f);
    p = fmaf(p, f, 5.550332471162809e-2f);
    p = fmaf(p, f, 2.402264791363012e-1f);
    p = fmaf(p, f, 6.931472028550421e-1f);
    p = fmaf(p, f, 1.0f);
    uint32_t sc = ((uint32_t)(int)(fl + 127.0f)) << 23;
    return p * __uint_as_float(sc);
}

// ---------------------------------------------------------------------------
// Pre-pass: tf32 rounding (elementwise) and transpose+round for weights.
// ---------------------------------------------------------------------------
__global__ void __launch_bounds__(256) round_tf32(
    const float* __restrict__ in, uint32_t* __restrict__ out, int n4)
{
    int i = blockIdx.x * 256 + threadIdx.x;
    if (i >= n4) return;
    float4 v = ((const float4*)in)[i];
    uint4 t = {f2tf32(v.x), f2tf32(v.y), f2tf32(v.z), f2tf32(v.w)};
    ((uint4*)out)[i] = t;
}

// W [K][N] fp32 -> Wt [N][K] tf32 bits (32x32 smem transpose)
__global__ void __launch_bounds__(256) transpose_round(
    const float* __restrict__ W, uint32_t* __restrict__ Wt, int K, int N)
{
    __shared__ float t[32][33];
    const int k0 = blockIdx.y * 32, n0 = blockIdx.x * 32;
    const int r = threadIdx.x >> 3, c4 = (threadIdx.x & 7) * 4;
    float4 v = *(const float4*)(W + (size_t)(k0 + r) * N + n0 + c4);
    t[r][c4] = v.x; t[r][c4+1] = v.y; t[r][c4+2] = v.z; t[r][c4+3] = v.w;
    __syncthreads();
    uint4 o = {f2tf32(t[c4][r]), f2tf32(t[c4+1][r]),
               f2tf32(t[c4+2][r]), f2tf32(t[c4+3][r])};
    *(uint4*)(Wt + (size_t)(n0 + r) * K + k0 + c4) = o;
}

// ---------------------------------------------------------------------------
// TF32 GEMM, both operands K-major pre-rounded: cp.async double-buffered,
// all fragments via ldmatrix.x4. Stride 36 u32 (==4 mod 32) conflict-free.
// ---------------------------------------------------------------------------
#define GPQ 36
#define GSTG (128 * GPQ)                   // u32 per operand per stage
#define GEMM_SMEM_BYTES (2 * 2 * GSTG * 4) // 2 stages x (A+B) = 73728 B

template<bool ROUND_OUT>
__global__ void __launch_bounds__(256) gemm_tf32ca(
    const uint32_t* __restrict__ A, const uint32_t* __restrict__ Bt,
    const float* __restrict__ bias, float* __restrict__ C, int K, int N)
{
    extern __shared__ uint32_t sm[];
    const int tid  = threadIdx.x;
    const int warp = tid >> 5, lane = tid & 31;
    const int wm = warp >> 2, wn = warp & 3;
    const int g  = lane >> 2, tg = lane & 3;
    const int m0 = blockIdx.y * 128;
    const int n0 = blockIdx.x * 128;
    const uint32_t smb = sm_addr(sm);

    const int l15 = lane & 15;
    const int ahalfb = (lane >> 4) * 16;
    uint32_t aA[4];
    #pragma unroll
    for (int mt = 0; mt < 4; mt++)
        aA[mt] = smb + ((wm * 64 + mt * 16 + l15) * GPQ) * 4 + ahalfb;
    const int brow = (lane & 7) + ((lane >> 4) & 1) * 8;
    const int bcolb = ((lane >> 3) & 1) * 16;
    uint32_t bA[2];
    #pragma unroll
    for (int p = 0; p < 2; p++)
        bA[p] = smb + (GSTG + (wn * 32 + p * 16 + brow) * GPQ) * 4 + bcolb;

    // staging: tile row = 32 u32 = 8 x 16B segs; 128 rows x 8 = 1024 cp16/operand
    const int sr = tid >> 3, ss = (tid & 7) * 4;

    float acc[4][4][4];
    #pragma unroll
    for (int i = 0; i < 4; i++)
        #pragma unroll
        for (int j = 0; j < 4; j++)
            #pragma unroll
            for (int c = 0; c < 4; c++) acc[i][j][c] = 0.f;

    const int nkc = K / 32;
    #pragma unroll
    for (int i = 0; i < 4; i++) {
        const int row = sr + 32 * i;
        cp16(smb + (row * GPQ + ss) * 4, A + (size_t)(m0 + row) * K + ss);
        cp16(smb + (GSTG + row * GPQ + ss) * 4, Bt + (size_t)(n0 + row) * K + ss);
    }
    cp_commit();

    for (int kc = 0; kc < nkc; kc++) {
        const uint32_t soff = (kc & 1) ? (2u * GSTG * 4u) : 0u;
        if (kc + 1 < nkc) {
            const uint32_t noff = ((kc + 1) & 1) ? (2u * GSTG * 4u) : 0u;
            #pragma unroll
            for (int i = 0; i < 4; i++) {
                const int row = sr + 32 * i;
                cp16(smb + noff + (row * GPQ + ss) * 4,
                     A + (size_t)(m0 + row) * K + (kc + 1) * 32 + ss);
                cp16(smb + noff + (GSTG + row * GPQ + ss) * 4,
                     Bt + (size_t)(n0 + row) * K + (kc + 1) * 32 + ss);
            }
            cp_commit();
            cp_wait<1>();
        } else {
            cp_wait<0>();
        }
        __syncthreads();

        #pragma unroll
        for (int ks = 0; ks < 4; ks++) {
            uint32_t a[4][4], b01[4], b23[4];
            #pragma unroll
            for (int mt = 0; mt < 4; mt++)
                ldsm4(a[mt], aA[mt] + soff + ks * 32);
            ldsm4(b01, bA[0] + soff + ks * 32);
            ldsm4(b23, bA[1] + soff + ks * 32);
            #pragma unroll
            for (int mt = 0; mt < 4; mt++) {
                mma8(acc[mt][0], a[mt][0], a[mt][1], a[mt][2], a[mt][3], b01[0], b01[1]);
                mma8(acc[mt][1], a[mt][0], a[mt][1], a[mt][2], a[mt][3], b01[2], b01[3]);
                mma8(acc[mt][2], a[mt][0], a[mt][1], a[mt][2], a[mt][3], b23[0], b23[1]);
                mma8(acc[mt][3], a[mt][0], a[mt][1], a[mt][2], a[mt][3], b23[2], b23[3]);
            }
        }
        __syncthreads();
    }

    #pragma unroll
    for (int nt = 0; nt < 4; nt++) {
        const int col = n0 + wn * 32 + nt * 8 + 2 * tg;
        float2 bv = *(const float2*)(bias + col);
        #pragma unroll
        for (int mt = 0; mt < 4; mt++) {
            const int row0 = m0 + wm * 64 + mt * 16 + g;
            float v0 = acc[mt][nt][0] + bv.x, v1 = acc[mt][nt][1] + bv.y;
            float v2 = acc[mt][nt][2] + bv.x, v3 = acc[mt][nt][3] + bv.y;
            if (ROUND_OUT) {
                v0 = __uint_as_float(f2tf32(v0));
                v1 = __uint_as_float(f2tf32(v1));
                v2 = __uint_as_float(f2tf32(v2));
                v3 = __uint_as_float(f2tf32(v3));
            }
            *(float2*)(C + (size_t)row0 * N + col)       = make_float2(v0, v1);
            *(float2*)(C + (size_t)(row0 + 8) * N + col) = make_float2(v2, v3);
        }
    }
}

// ---------------------------------------------------------------------------
// Causal MQA flash attention: single-pass TF32, BQ=128 x BK=64, cp.async
// in-place prefetch (K overlaps softmax+PV, V overlaps next S-phase),
// ldmatrix Q/K/P frags. Inputs pre-rounded (no cvt on staging).
// FIX vs r10: Q/K/V rows are 128 floats = 32 x 16B segments (not 8).
// ---------------------------------------------------------------------------
#define PQ 132
#define PV 136
#define PS 68

#define OFF_Q 0
#define OFF_K (OFF_Q + 128*PQ)
#define OFF_V (OFF_K + 64*PQ)
#define OFF_S (OFF_V + 64*PV)
#define OFF_M (OFF_S + 128*PS)
#define ATTN_U32 (OFF_M + 3*128)
#define ATTN_SMEM_BYTES (ATTN_U32 * 4)    // 172,544 B

__global__ void __launch_bounds__(256) mqa_attn_tf32(
    const float* __restrict__ qkv, float* __restrict__ out)
{
    extern __shared__ uint32_t smem_u[];
    uint32_t* Qs = smem_u + OFF_Q;
    uint32_t* Ks = smem_u + OFF_K;
    uint32_t* Vs = smem_u + OFF_V;
    float*    Sf = (float*)(smem_u + OFF_S);
    uint32_t* Su = smem_u + OFF_S;
    float* m_s = (float*)(smem_u + OFF_M);
    float* l_s = m_s + 128;
    float* f_s = l_s + 128;

    const int tid  = threadIdx.x;
    const int warp = tid >> 5, lane = tid & 31;
    const int g = lane >> 2, tg = lane & 3;
    const int wm = warp >> 1, wn = warp & 1;
    const int qt = gridDim.x - 1 - blockIdx.x;
    const int h = blockIdx.y, b = blockIdx.z;
    const int q0 = qt * 128;

    const float* qbase = qkv + (size_t)b * SEQ * NQKV + h * HD;
    const float* kbase = qkv + (size_t)b * SEQ * NQKV + H;
    const float* vbase = kbase + HD;

    const int l15 = lane & 15;
    const int ahalfb = (lane >> 4) * 16;
    const int brow  = (lane & 7) + ((lane >> 4) & 1) * 8;
    const int bcolb = ((lane >> 3) & 1) * 16;
    uint32_t qA[2], pA[2], kA[2];
    #pragma unroll
    for (int mt = 0; mt < 2; mt++) {
        const int row = wm * 32 + mt * 16 + l15;
        qA[mt] = sm_addr(Qs) + (row * PQ) * 4 + ahalfb;
        pA[mt] = sm_addr(Su) + (row * PS) * 4 + ahalfb;
    }
    #pragma unroll
    for (int p = 0; p < 2; p++)
        kA[p] = sm_addr(Ks) + ((wn * 32 + p * 16 + brow) * PQ) * 4 + bcolb;

    // prologue: Q (group 0, 4096 cp16), K0 (group 1, 2048), V0 (group 2, 2048)
    #pragma unroll
    for (int i = 0; i < 16; i++) {
        const int idx = tid + i * 256;
        const int r = idx >> 5, sg = (idx & 31) * 4;
        cp16(sm_addr(Qs) + (r * PQ + sg) * 4, qbase + (size_t)(q0 + r) * NQKV + sg);
    }
    cp_commit();
    #pragma unroll
    for (int i = 0; i < 8; i++) {
        const int idx = tid + i * 256;
        const int r = idx >> 5, sg = (idx & 31) * 4;
        cp16(sm_addr(Ks) + (r * PQ + sg) * 4, kbase + (size_t)r * NQKV + sg);
    }
    cp_commit();
    #pragma unroll
    for (int i = 0; i < 8; i++) {
        const int idx = tid + i * 256;
        const int r = idx >> 5, sg = (idx & 31) * 4;
        cp16(sm_addr(Vs) + (r * PV + sg) * 4, vbase + (size_t)r * NQKV + sg);
    }
    cp_commit();

    if (tid < 128) { m_s[tid] = -1e30f; l_s[tid] = 0.f; }

    float o[2][8][4];
    #pragma unroll
    for (int mt = 0; mt < 2; mt++)
        #pragma unroll
        for (int nt = 0; nt < 8; nt++)
            #pragma unroll
            for (int c = 0; c < 4; c++) o[mt][nt][c] = 0.f;

    const int nkt = 2 * qt + 2;
    for (int kt = 0; kt < nkt; kt++) {
        const int k0 = kt * 64;
        cp_wait<1>();        // K(kt) arrived (V(kt) may still be in flight)
        __syncthreads();

        // ---- S = Q @ K^T (128x64), warp tile 32x32, 16 k8-steps ----
        float sacc[2][4][4];
        #pragma unroll
        for (int mt = 0; mt < 2; mt++)
            #pragma unroll
            for (int nt = 0; nt < 4; nt++)
                #pragma unroll
                for (int c = 0; c < 4; c++) sacc[mt][nt][c] = 0.f;

        #pragma unroll
        for (int ks = 0; ks < 16; ks++) {
            uint32_t a[2][4], b01[4], b23[4];
            ldsm4(a[0], qA[0] + ks * 32);
            ldsm4(a[1], qA[1] + ks * 32);
            ldsm4(b01, kA[0] + ks * 32);
            ldsm4(b23, kA[1] + ks * 32);
            #pragma unroll
            for (int mt = 0; mt < 2; mt++) {
                mma8(sacc[mt][0], a[mt][0], a[mt][1], a[mt][2], a[mt][3], b01[0], b01[1]);
                mma8(sacc[mt][1], a[mt][0], a[mt][1], a[mt][2], a[mt][3], b01[2], b01[3]);
                mma8(sacc[mt][2], a[mt][0], a[mt][1], a[mt][2], a[mt][3], b23[0], b23[1]);
                mma8(sacc[mt][3], a[mt][0], a[mt][1], a[mt][2], a[mt][3], b23[2], b23[3]);
            }
        }

        const bool need_mask = (k0 + 63 > q0 + wm * 32);
        #pragma unroll
        for (int mt = 0; mt < 2; mt++) {
            const int mb = wm * 32 + mt * 16;
            #pragma unroll
            for (int nt = 0; nt < 4; nt++) {
                const int nb = wn * 32 + nt * 8;
                const int c0 = nb + 2 * tg, c1 = c0 + 1;
                const int r0 = mb + g, r1 = mb + g + 8;
                float s00 = sacc[mt][nt][0] * SCALE;
                float s01 = sacc[mt][nt][1] * SCALE;
                float s10 = sacc[mt][nt][2] * SCALE;
                float s11 = sacc[mt][nt][3] * SCALE;
                if (need_mask) {
                    if (k0 + c0 > q0 + r0) s00 = -1e30f;
                    if (k0 + c1 > q0 + r0) s01 = -1e30f;
                    if (k0 + c0 > q0 + r1) s10 = -1e30f;
                    if (k0 + c1 > q0 + r1) s11 = -1e30f;
                }
                Sf[r0*PS + c0] = s00;  Sf[r0*PS + c1] = s01;
                Sf[r1*PS + c0] = s10;  Sf[r1*PS + c1] = s11;
            }
        }
        __syncthreads();

        // prefetch next K (overlaps softmax + PV)
        if (kt + 1 < nkt) {
            #pragma unroll
            for (int i = 0; i < 8; i++) {
                const int idx = tid + i * 256;
                const int r = idx >> 5, sg = (idx & 31) * 4;
                cp16(sm_addr(Ks) + (r * PQ + sg) * 4,
                     kbase + (size_t)(k0 + 64 + r) * NQKV + sg);
            }
            cp_commit();
        }

        // ---- online softmax: 2 threads/row; P written back as tf32 ----
        {
            const int row = tid >> 1, sub = tid & 1;
            float* srow = Sf + row*PS + sub*32;
            uint32_t* urow = Su + row*PS + sub*32;
            float mold = m_s[row];
            float mx = mold;
            #pragma unroll
            for (int c = 0; c < 8; c++) {
                float4 t = *(float4*)&srow[4*c];
                mx = fmaxf(mx, fmaxf(fmaxf(t.x, t.y), fmaxf(t.z, t.w)));
            }
            mx = fmaxf(mx, __shfl_xor_sync(0xffffffffu, mx, 1));
            float sum = 0.f;
            #pragma unroll
            for (int j = 0; j < 8; j++) {
                float4 t = *(float4*)&srow[4*j];
                float p0 = fast_exp(t.x - mx), p1 = fast_exp(t.y - mx);
                float p2 = fast_exp(t.z - mx), p3 = fast_exp(t.w - mx);
                sum += (p0 + p1) + (p2 + p3);
                uint4 u = {f2tf32(p0), f2tf32(p1), f2tf32(p2), f2tf32(p3)};
                *(uint4*)&urow[4*j] = u;
            }
            sum += __shfl_xor_sync(0xffffffffu, sum, 1);
            if (sub == 0) {
                float f = fast_exp(mold - mx);
                l_s[row] = l_s[row] * f + sum;
                m_s[row] = mx;
                f_s[row] = f;
            }
        }
        if (kt + 1 < nkt) cp_wait<1>();   // V(kt) arrived (K(kt+1) in flight)
        else              cp_wait<0>();
        __syncthreads();

        // ---- O = O*f + P @ V (128x128), warp tile 32x64, 8 k8-steps ----
        float fr[2][2];
        #pragma unroll
        for (int mt = 0; mt < 2; mt++) {
            const int mb = wm * 32 + mt * 16;
            fr[mt][0] = f_s[mb + g];
            fr[mt][1] = f_s[mb + g + 8];
        }
        #pragma unroll
        for (int mt = 0; mt < 2; mt++)
            #pragma unroll
            for (int nt = 0; nt < 8; nt++) {
                o[mt][nt][0] *= fr[mt][0];  o[mt][nt][1] *= fr[mt][0];
                o[mt][nt][2] *= fr[mt][1];  o[mt][nt][3] *= fr[mt][1];
            }

        #pragma unroll
        for (int ks = 0; ks < 8; ks++) {
            const int kb = ks * 8;
            uint32_t a[2][4];
            ldsm4(a[0], pA[0] + ks * 32);
            ldsm4(a[1], pA[1] + ks * 32);
            #pragma unroll
            for (int nt = 0; nt < 8; nt++) {
                const int nb = wn * 64 + nt * 8;
                uint32_t b0 = Vs[(kb + tg    )*PV + nb + g];
                uint32_t b1 = Vs[(kb + tg + 4)*PV + nb + g];
                #pragma unroll
                for (int mt = 0; mt < 2; mt++)
                    mma8(o[mt][nt], a[mt][0], a[mt][1], a[mt][2], a[mt][3], b0, b1);
            }
        }
        __syncthreads();

        // prefetch next V (overlaps next S-phase)
        if (kt + 1 < nkt) {
            #pragma unroll
            for (int i = 0; i < 8; i++) {
                const int idx = tid + i * 256;
                const int r = idx >> 5, sg = (idx & 31) * 4;
                cp16(sm_addr(Vs) + (r * PV + sg) * 4,
                     vbase + (size_t)(k0 + 64 + r) * NQKV + sg);
            }
            cp_commit();
        }
    }

    // final write: o / l, tf32-rounded for the proj GEMM's raw-bits path
    #pragma unroll
    for (int mt = 0; mt < 2; mt++) {
        const int mb = wm * 32 + mt * 16;
        const float inv0 = 1.f / l_s[mb + g];
        const float inv1 = 1.f / l_s[mb + g + 8];
        #pragma unroll
        for (int nt = 0; nt < 8; nt++) {
            const int col = wn * 64 + nt * 8 + 2 * tg;
            size_t row0 = (size_t)(b * SEQ + q0 + mb + g) * H + h * HD + col;
            size_t row1 = (size_t)(b * SEQ + q0 + mb + g + 8) * H + h * HD + col;
            float2 r0 = {__uint_as_float(f2tf32(o[mt][nt][0] * inv0)),
                         __uint_as_float(f2tf32(o[mt][nt][1] * inv0))};
            float2 r1 = {__uint_as_float(f2tf32(o[mt][nt][2] * inv1)),
                         __uint_as_float(f2tf32(o[mt][nt][3] * inv1))};
            *(float2*)(out + row0) = r0;
            *(float2*)(out + row1) = r1;
        }
    }
}

// ---------------------------------------------------------------------------

extern "C" void kernel_launch(void* const* d_in, const int* in_sizes, int n_in,
                              void* d_out, int out_size)
{
    (void)in_sizes; (void)n_in; (void)out_size;
    const float* x     = (const float*)d_in[0];
    const float* Wqkv  = (const float*)d_in[1];
    const float* bqkv  = (const float*)d_in[2];
    const float* Wproj = (const float*)d_in[3];
    const float* bproj = (const float*)d_in[4];
    float* out = (float*)d_out;

    float *qkv_p, *attn_p;
    uint32_t *xt, *wqt, *wpt;
    cudaGetSymbolAddress((void**)&qkv_p, g_qkv);
    cudaGetSymbolAddress((void**)&attn_p, g_attn);
    cudaGetSymbolAddress((void**)&xt, g_xt);
    cudaGetSymbolAddress((void**)&wqt, g_wqt);
    cudaGetSymbolAddress((void**)&wpt, g_wpt);

    cudaFuncSetAttribute(mqa_attn_tf32, cudaFuncAttributeMaxDynamicSharedMemorySize,
                         ATTN_SMEM_BYTES);
    cudaFuncSetAttribute(gemm_tf32ca<true>, cudaFuncAttributeMaxDynamicSharedMemorySize,
                         GEMM_SMEM_BYTES);
    cudaFuncSetAttribute(gemm_tf32ca<false>, cudaFuncAttributeMaxDynamicSharedMemorySize,
                         GEMM_SMEM_BYTES);

    // 0) pre-round + pre-transpose
    round_tf32<<<(MROWS * H / 4 + 255) / 256, 256>>>(x, xt, MROWS * H / 4);
    transpose_round<<<dim3(NQKV / 32, H / 32), 256>>>(Wqkv, wqt, H, NQKV);
    transpose_round<<<dim3(H / 32, H / 32), 256>>>(Wproj, wpt, H, H);

    // 1) QKV GEMM (cp.async + full-ldmatrix TF32; output tf32-rounded)
    gemm_tf32ca<true><<<dim3(NQKV / 128, MROWS / 128), 256, GEMM_SMEM_BYTES>>>(
        xt, wqt, bqkv, qkv_p, H, NQKV);

    // 2) causal MQA flash attention (async-prefetch TF32)
    mqa_attn_tf32<<<dim3(SEQ / 128, NH, BATCH), 256, ATTN_SMEM_BYTES>>>(qkv_p, attn_p);

    // 3) proj GEMM -> d_out (fp32 output, no rounding)
    gemm_tf32ca<false><<<dim3(H / 128, MROWS / 128), 256, GEMM_SMEM_BYTES>>>(
        (const uint32_t*)attn_p, wpt, bproj, out, H, H);
}

// round 12
// speedup vs baseline: 1.1547x; 1.0127x over previous
#include <cuda_runtime.h>
#include <math.h>
#include <stdint.h>

#define H 2048
#define NH 16
#define HD 128
#define SEQ 2048
#define BATCH 2
#define NQKV (H + 2*HD)   // 2304
#define SCALE 0.08838834764831843f  // 1/sqrt(128)
#define MROWS (BATCH*SEQ)

// ---------------- global scratch (allocation-free rule) ----------------
__device__ float    g_qkv[(size_t)MROWS * NQKV];   // tf32-rounded qkv
__device__ float    g_attn[(size_t)MROWS * H];     // tf32-rounded attn out
__device__ uint32_t g_xt[(size_t)MROWS * H];       // x, tf32-rounded
__device__ uint32_t g_wqt[(size_t)NQKV * H];       // Wqkv^T [N][K] rounded
__device__ uint32_t g_wpt[(size_t)H * H];          // Wproj^T [N][K] rounded

// ---------------- helpers ----------------
__device__ __forceinline__ uint32_t f2tf32(float x) {
    uint32_t r;
    asm("cvt.rna.tf32.f32 %0, %1;" : "=r"(r) : "f"(x));
    return r;
}
__device__ __forceinline__ void mma8(float* c, uint32_t a0, uint32_t a1,
                                     uint32_t a2, uint32_t a3,
                                     uint32_t b0, uint32_t b1) {
    asm volatile(
        "mma.sync.aligned.m16n8k8.row.col.f32.tf32.tf32.f32 "
        "{%0,%1,%2,%3}, {%4,%5,%6,%7}, {%8,%9}, {%0,%1,%2,%3};"
        : "+f"(c[0]), "+f"(c[1]), "+f"(c[2]), "+f"(c[3])
        : "r"(a0), "r"(a1), "r"(a2), "r"(a3), "r"(b0), "r"(b1));
}
__device__ __forceinline__ void ldsm4(uint32_t* r, uint32_t addr) {
    asm volatile("ldmatrix.sync.aligned.m8n8.x4.shared.b16 {%0,%1,%2,%3}, [%4];"
        : "=r"(r[0]), "=r"(r[1]), "=r"(r[2]), "=r"(r[3]) : "r"(addr));
}
__device__ __forceinline__ uint32_t sm_addr(const void* p) {
    return (uint32_t)__cvta_generic_to_shared(p);
}
__device__ __forceinline__ void cp16(uint32_t dst, const void* src) {
    asm volatile("cp.async.cg.shared.global [%0], [%1], 16;" :: "r"(dst), "l"(src));
}
__device__ __forceinline__ void cp_commit() {
    asm volatile("cp.async.commit_group;");
}
template<int N>
__device__ __forceinline__ void cp_wait() {
    asm volatile("cp.async.wait_group %0;" :: "n"(N));
}
__device__ __forceinline__ float fast_exp(float x) {
    float t = fmaxf(x * 1.4426950408889634f, -126.0f);
    float fl = floorf(t);
    float f = t - fl;
    float p =              1.535336188319500e-4f;
    p = fmaf(p, f, 1.339887440266574e-3f);
    p = fmaf(p, f, 9.618437357674640e-3f);
    p = fmaf(p, f, 5.550332471162809e-2f);
    p = fmaf(p, f, 2.402264791363012e-1f);
    p = fmaf(p, f, 6.931472028550421e-1f);
    p = fmaf(p, f, 1.0f);
    uint32_t sc = ((uint32_t)(int)(fl + 127.0f)) << 23;
    return p * __uint_as_float(sc);
}

// ---------------------------------------------------------------------------
// Pre-pass: tf32 rounding (elementwise) and transpose+round for weights.
// ---------------------------------------------------------------------------
__global__ void __launch_bounds__(256) round_tf32(
    const float* __restrict__ in, uint32_t* __restrict__ out, int n4)
{
    int i = blockIdx.x * 256 + threadIdx.x;
    if (i >= n4) return;
    float4 v = ((const float4*)in)[i];
    uint4 t = {f2tf32(v.x), f2tf32(v.y), f2tf32(v.z), f2tf32(v.w)};
    ((uint4*)out)[i] = t;
}

// W [K][N] fp32 -> Wt [N][K] tf32 bits (32x32 smem transpose)
__global__ void __launch_bounds__(256) transpose_round(
    const float* __restrict__ W, uint32_t* __restrict__ Wt, int K, int N)
{
    __shared__ float t[32][33];
    const int k0 = blockIdx.y * 32, n0 = blockIdx.x * 32;
    const int r = threadIdx.x >> 3, c4 = (threadIdx.x & 7) * 4;
    float4 v = *(const float4*)(W + (size_t)(k0 + r) * N + n0 + c4);
    t[r][c4] = v.x; t[r][c4+1] = v.y; t[r][c4+2] = v.z; t[r][c4+3] = v.w;
    __syncthreads();
    uint4 o = {f2tf32(t[c4][r]), f2tf32(t[c4+1][r]),
               f2tf32(t[c4+2][r]), f2tf32(t[c4+3][r])};
    *(uint4*)(Wt + (size_t)(n0 + r) * K + k0 + c4) = o;
}

// ---------------------------------------------------------------------------
// TF32 GEMM: CTA tile 256x128, 512 threads (warp grid 8x2, warp tile 32x64),
// 3-stage cp.async pipeline (BK=32), ONE __syncthreads per chunk, all
// fragments via ldmatrix.x4. Stride 36 u32 (==4 mod 32) conflict-free.
// ---------------------------------------------------------------------------
#define GPQ 36
#define GSA (256 * GPQ)            // A stage u32
#define GSB (128 * GPQ)            // B stage u32
#define GST (GSA + GSB)            // stage total u32 (13824)
#define GEMM_SMEM_BYTES (3 * GST * 4)   // 165,888 B

template<bool ROUND_OUT>
__global__ void __launch_bounds__(512) gemm_tf32ca(
    const uint32_t* __restrict__ A, const uint32_t* __restrict__ Bt,
    const float* __restrict__ bias, float* __restrict__ C, int K, int N)
{
    extern __shared__ uint32_t sm[];
    const int tid  = threadIdx.x;
    const int warp = tid >> 5, lane = tid & 31;
    const int wm = warp >> 1, wn = warp & 1;     // 8 x 2 warp grid
    const int g  = lane >> 2, tg = lane & 3;
    const int m0 = blockIdx.y * 256;
    const int n0 = blockIdx.x * 128;
    const uint32_t smb = sm_addr(sm);

    // fragment byte addresses within a stage (stage offset added per use)
    const int l15 = lane & 15;
    const int ahalfb = (lane >> 4) * 16;
    uint32_t aA[2];
    #pragma unroll
    for (int mt = 0; mt < 2; mt++)
        aA[mt] = smb + ((wm * 32 + mt * 16 + l15) * GPQ) * 4 + ahalfb;
    const int brow = (lane & 7) + ((lane >> 4) & 1) * 8;
    const int bcolb = ((lane >> 3) & 1) * 16;
    uint32_t bA[4];
    #pragma unroll
    for (int p = 0; p < 4; p++)
        bA[p] = smb + (GSA + (wn * 64 + p * 16 + brow) * GPQ) * 4 + bcolb;

    // staging: rows of 32 u32 = 8 x 16B segs. A: 2048 cp16 (4/thr), B: 1024 (2/thr)
    const int sr = tid >> 3, ss = (tid & 7) * 4;   // sr 0..63

    float acc[2][8][4];
    #pragma unroll
    for (int i = 0; i < 2; i++)
        #pragma unroll
        for (int j = 0; j < 8; j++)
            #pragma unroll
            for (int c = 0; c < 4; c++) acc[i][j][c] = 0.f;

    const int nkc = K / 32;

    // prologue: stages 0 and 1
    #pragma unroll
    for (int s = 0; s < 2; s++) {
        const uint32_t off = s * GST * 4;
        #pragma unroll
        for (int i = 0; i < 4; i++) {
            const int row = sr + 64 * i;
            cp16(smb + off + (row * GPQ + ss) * 4,
                 A + (size_t)(m0 + row) * K + s * 32 + ss);
        }
        #pragma unroll
        for (int i = 0; i < 2; i++) {
            const int row = sr + 64 * i;
            cp16(smb + off + (GSA + row * GPQ + ss) * 4,
                 Bt + (size_t)(n0 + row) * K + s * 32 + ss);
        }
        cp_commit();
    }

    for (int kc = 0; kc < nkc; kc++) {
        const uint32_t soff = (uint32_t)(kc % 3) * GST * 4;
        if (kc + 1 < nkc) cp_wait<1>();
        else              cp_wait<0>();
        __syncthreads();   // single barrier per chunk (3-stage ring)

        if (kc + 2 < nkc) {
            const uint32_t noff = (uint32_t)((kc + 2) % 3) * GST * 4;
            #pragma unroll
            for (int i = 0; i < 4; i++) {
                const int row = sr + 64 * i;
                cp16(smb + noff + (row * GPQ + ss) * 4,
                     A + (size_t)(m0 + row) * K + (kc + 2) * 32 + ss);
            }
            #pragma unroll
            for (int i = 0; i < 2; i++) {
                const int row = sr + 64 * i;
                cp16(smb + noff + (GSA + row * GPQ + ss) * 4,
                     Bt + (size_t)(n0 + row) * K + (kc + 2) * 32 + ss);
            }
            cp_commit();
        }

        #pragma unroll
        for (int ks = 0; ks < 4; ks++) {
            uint32_t a[2][4], b[4][4];
            #pragma unroll
            for (int mt = 0; mt < 2; mt++)
                ldsm4(a[mt], aA[mt] + soff + ks * 32);
            #pragma unroll
            for (int p = 0; p < 4; p++)
                ldsm4(b[p], bA[p] + soff + ks * 32);
            #pragma unroll
            for (int mt = 0; mt < 2; mt++)
                #pragma unroll
                for (int nt = 0; nt < 8; nt++)
                    mma8(acc[mt][nt], a[mt][0], a[mt][1], a[mt][2], a[mt][3],
                         b[nt >> 1][(nt & 1) * 2], b[nt >> 1][(nt & 1) * 2 + 1]);
        }
    }

    #pragma unroll
    for (int nt = 0; nt < 8; nt++) {
        const int col = n0 + wn * 64 + nt * 8 + 2 * tg;
        float2 bv = *(const float2*)(bias + col);
        #pragma unroll
        for (int mt = 0; mt < 2; mt++) {
            const int row0 = m0 + wm * 32 + mt * 16 + g;
            float v0 = acc[mt][nt][0] + bv.x, v1 = acc[mt][nt][1] + bv.y;
            float v2 = acc[mt][nt][2] + bv.x, v3 = acc[mt][nt][3] + bv.y;
            if (ROUND_OUT) {
                v0 = __uint_as_float(f2tf32(v0));
                v1 = __uint_as_float(f2tf32(v1));
                v2 = __uint_as_float(f2tf32(v2));
                v3 = __uint_as_float(f2tf32(v3));
            }
            *(float2*)(C + (size_t)row0 * N + col)       = make_float2(v0, v1);
            *(float2*)(C + (size_t)(row0 + 8) * N + col) = make_float2(v2, v3);
        }
    }
}

// ---------------------------------------------------------------------------
// Causal MQA flash attention (round-11, unchanged): single-pass TF32,
// BQ=128 x BK=64, cp.async in-place prefetch, ldmatrix Q/K/P frags.
// ---------------------------------------------------------------------------
#define PQ 132
#define PV 136
#define PS 68

#define OFF_Q 0
#define OFF_K (OFF_Q + 128*PQ)
#define OFF_V (OFF_K + 64*PQ)
#define OFF_S (OFF_V + 64*PV)
#define OFF_M (OFF_S + 128*PS)
#define ATTN_U32 (OFF_M + 3*128)
#define ATTN_SMEM_BYTES (ATTN_U32 * 4)    // 172,544 B

__global__ void __launch_bounds__(256) mqa_attn_tf32(
    const float* __restrict__ qkv, float* __restrict__ out)
{
    extern __shared__ uint32_t smem_u[];
    uint32_t* Qs = smem_u + OFF_Q;
    uint32_t* Ks = smem_u + OFF_K;
    uint32_t* Vs = smem_u + OFF_V;
    float*    Sf = (float*)(smem_u + OFF_S);
    uint32_t* Su = smem_u + OFF_S;
    float* m_s = (float*)(smem_u + OFF_M);
    float* l_s = m_s + 128;
    float* f_s = l_s + 128;

    const int tid  = threadIdx.x;
    const int warp = tid >> 5, lane = tid & 31;
    const int g = lane >> 2, tg = lane & 3;
    const int wm = warp >> 1, wn = warp & 1;
    const int qt = gridDim.x - 1 - blockIdx.x;
    const int h = blockIdx.y, b = blockIdx.z;
    const int q0 = qt * 128;

    const float* qbase = qkv + (size_t)b * SEQ * NQKV + h * HD;
    const float* kbase = qkv + (size_t)b * SEQ * NQKV + H;
    const float* vbase = kbase + HD;

    const int l15 = lane & 15;
    const int ahalfb = (lane >> 4) * 16;
    const int brow  = (lane & 7) + ((lane >> 4) & 1) * 8;
    const int bcolb = ((lane >> 3) & 1) * 16;
    uint32_t qA[2], pA[2], kA[2];
    #pragma unroll
    for (int mt = 0; mt < 2; mt++) {
        const int row = wm * 32 + mt * 16 + l15;
        qA[mt] = sm_addr(Qs) + (row * PQ) * 4 + ahalfb;
        pA[mt] = sm_addr(Su) + (row * PS) * 4 + ahalfb;
    }
    #pragma unroll
    for (int p = 0; p < 2; p++)
        kA[p] = sm_addr(Ks) + ((wn * 32 + p * 16 + brow) * PQ) * 4 + bcolb;

    // prologue: Q (group 0), K0 (group 1), V0 (group 2)
    #pragma unroll
    for (int i = 0; i < 16; i++) {
        const int idx = tid + i * 256;
        const int r = idx >> 5, sg = (idx & 31) * 4;
        cp16(sm_addr(Qs) + (r * PQ + sg) * 4, qbase + (size_t)(q0 + r) * NQKV + sg);
    }
    cp_commit();
    #pragma unroll
    for (int i = 0; i < 8; i++) {
        const int idx = tid + i * 256;
        const int r = idx >> 5, sg = (idx & 31) * 4;
        cp16(sm_addr(Ks) + (r * PQ + sg) * 4, kbase + (size_t)r * NQKV + sg);
    }
    cp_commit();
    #pragma unroll
    for (int i = 0; i < 8; i++) {
        const int idx = tid + i * 256;
        const int r = idx >> 5, sg = (idx & 31) * 4;
        cp16(sm_addr(Vs) + (r * PV + sg) * 4, vbase + (size_t)r * NQKV + sg);
    }
    cp_commit();

    if (tid < 128) { m_s[tid] = -1e30f; l_s[tid] = 0.f; }

    float o[2][8][4];
    #pragma unroll
    for (int mt = 0; mt < 2; mt++)
        #pragma unroll
        for (int nt = 0; nt < 8; nt++)
            #pragma unroll
            for (int c = 0; c < 4; c++) o[mt][nt][c] = 0.f;

    const int nkt = 2 * qt + 2;
    for (int kt = 0; kt < nkt; kt++) {
        const int k0 = kt * 64;
        cp_wait<1>();        // K(kt) arrived (V(kt) may still be in flight)
        __syncthreads();

        // ---- S = Q @ K^T (128x64), warp tile 32x32, 16 k8-steps ----
        float sacc[2][4][4];
        #pragma unroll
        for (int mt = 0; mt < 2; mt++)
            #pragma unroll
            for (int nt = 0; nt < 4; nt++)
                #pragma unroll
                for (int c = 0; c < 4; c++) sacc[mt][nt][c] = 0.f;

        #pragma unroll
        for (int ks = 0; ks < 16; ks++) {
            uint32_t a[2][4], b01[4], b23[4];
            ldsm4(a[0], qA[0] + ks * 32);
            ldsm4(a[1], qA[1] + ks * 32);
            ldsm4(b01, kA[0] + ks * 32);
            ldsm4(b23, kA[1] + ks * 32);
            #pragma unroll
            for (int mt = 0; mt < 2; mt++) {
                mma8(sacc[mt][0], a[mt][0], a[mt][1], a[mt][2], a[mt][3], b01[0], b01[1]);
                mma8(sacc[mt][1], a[mt][0], a[mt][1], a[mt][2], a[mt][3], b01[2], b01[3]);
                mma8(sacc[mt][2], a[mt][0], a[mt][1], a[mt][2], a[mt][3], b23[0], b23[1]);
                mma8(sacc[mt][3], a[mt][0], a[mt][1], a[mt][2], a[mt][3], b23[2], b23[3]);
            }
        }

        const bool need_mask = (k0 + 63 > q0 + wm * 32);
        #pragma unroll
        for (int mt = 0; mt < 2; mt++) {
            const int mb = wm * 32 + mt * 16;
            #pragma unroll
            for (int nt = 0; nt < 4; nt++) {
                const int nb = wn * 32 + nt * 8;
                const int c0 = nb + 2 * tg, c1 = c0 + 1;
                const int r0 = mb + g, r1 = mb + g + 8;
                float s00 = sacc[mt][nt][0] * SCALE;
                float s01 = sacc[mt][nt][1] * SCALE;
                float s10 = sacc[mt][nt][2] * SCALE;
                float s11 = sacc[mt][nt][3] * SCALE;
                if (need_mask) {
                    if (k0 + c0 > q0 + r0) s00 = -1e30f;
                    if (k0 + c1 > q0 + r0) s01 = -1e30f;
                    if (k0 + c0 > q0 + r1) s10 = -1e30f;
                    if (k0 + c1 > q0 + r1) s11 = -1e30f;
                }
                Sf[r0*PS + c0] = s00;  Sf[r0*PS + c1] = s01;
                Sf[r1*PS + c0] = s10;  Sf[r1*PS + c1] = s11;
            }
        }
        __syncthreads();

        // prefetch next K (overlaps softmax + PV)
        if (kt + 1 < nkt) {
            #pragma unroll
            for (int i = 0; i < 8; i++) {
                const int idx = tid + i * 256;
                const int r = idx >> 5, sg = (idx & 31) * 4;
                cp16(sm_addr(Ks) + (r * PQ + sg) * 4,
                     kbase + (size_t)(k0 + 64 + r) * NQKV + sg);
            }
            cp_commit();
        }

        // ---- online softmax: 2 threads/row; P written back as tf32 ----
        {
            const int row = tid >> 1, sub = tid & 1;
            float* srow = Sf + row*PS + sub*32;
            uint32_t* urow = Su + row*PS + sub*32;
            float mold = m_s[row];
            float mx = mold;
            #pragma unroll
            for (int c = 0; c < 8; c++) {
                float4 t = *(float4*)&srow[4*c];
                mx = fmaxf(mx, fmaxf(fmaxf(t.x, t.y), fmaxf(t.z, t.w)));
            }
            mx = fmaxf(mx, __shfl_xor_sync(0xffffffffu, mx, 1));
            float sum = 0.f;
            #pragma unroll
            for (int j = 0; j < 8; j++) {
                float4 t = *(float4*)&srow[4*j];
                float p0 = fast_exp(t.x - mx), p1 = fast_exp(t.y - mx);
                float p2 = fast_exp(t.z - mx), p3 = fast_exp(t.w - mx);
                sum += (p0 + p1) + (p2 + p3);
                uint4 u = {f2tf32(p0), f2tf32(p1), f2tf32(p2), f2tf32(p3)};
                *(uint4*)&urow[4*j] = u;
            }
            sum += __shfl_xor_sync(0xffffffffu, sum, 1);
            if (sub == 0) {
                float f = fast_exp(mold - mx);
                l_s[row] = l_s[row] * f + sum;
                m_s[row] = mx;
                f_s[row] = f;
            }
        }
        if (kt + 1 < nkt) cp_wait<1>();   // V(kt) arrived (K(kt+1) in flight)
        else              cp_wait<0>();
        __syncthreads();

        // ---- O = O*f + P @ V (128x128), warp tile 32x64, 8 k8-steps ----
        float fr[2][2];
        #pragma unroll
        for (int mt = 0; mt < 2; mt++) {
            const int mb = wm * 32 + mt * 16;
            fr[mt][0] = f_s[mb + g];
            fr[mt][1] = f_s[mb + g + 8];
        }
        #pragma unroll
        for (int mt = 0; mt < 2; mt++)
            #pragma unroll
            for (int nt = 0; nt < 8; nt++) {
                o[mt][nt][0] *= fr[mt][0];  o[mt][nt][1] *= fr[mt][0];
                o[mt][nt][2] *= fr[mt][1];  o[mt][nt][3] *= fr[mt][1];
            }

        #pragma unroll
        for (int ks = 0; ks < 8; ks++) {
            const int kb = ks * 8;
            uint32_t a[2][4];
            ldsm4(a[0], pA[0] + ks * 32);
            ldsm4(a[1], pA[1] + ks * 32);
            #pragma unroll
            for (int nt = 0; nt < 8; nt++) {
                const int nb = wn * 64 + nt * 8;
                uint32_t b0 = Vs[(kb + tg    )*PV + nb + g];
                uint32_t b1 = Vs[(kb + tg + 4)*PV + nb + g];
                #pragma unroll
                for (int mt = 0; mt < 2; mt++)
                    mma8(o[mt][nt], a[mt][0], a[mt][1], a[mt][2], a[mt][3], b0, b1);
            }
        }
        __syncthreads();

        // prefetch next V (overlaps next S-phase)
        if (kt + 1 < nkt) {
            #pragma unroll
            for (int i = 0; i < 8; i++) {
                const int idx = tid + i * 256;
                const int r = idx >> 5, sg = (idx & 31) * 4;
                cp16(sm_addr(Vs) + (r * PV + sg) * 4,
                     vbase + (size_t)(k0 + 64 + r) * NQKV + sg);
            }
            cp_commit();
        }
    }

    // final write: o / l, tf32-rounded for the proj GEMM's raw-bits path
    #pragma unroll
    for (int mt = 0; mt < 2; mt++) {
        const int mb = wm * 32 + mt * 16;
        const float inv0 = 1.f / l_s[mb + g];
        const float inv1 = 1.f / l_s[mb + g + 8];
        #pragma unroll
        for (int nt = 0; nt < 8; nt++) {
            const int col = wn * 64 + nt * 8 + 2 * tg;
            size_t row0 = (size_t)(b * SEQ + q0 + mb + g) * H + h * HD + col;
            size_t row1 = (size_t)(b * SEQ + q0 + mb + g + 8) * H + h * HD + col;
            float2 r0 = {__uint_as_float(f2tf32(o[mt][nt][0] * inv0)),
                         __uint_as_float(f2tf32(o[mt][nt][1] * inv0))};
            float2 r1 = {__uint_as_float(f2tf32(o[mt][nt][2] * inv1)),
                         __uint_as_float(f2tf32(o[mt][nt][3] * inv1))};
            *(float2*)(out + row0) = r0;
            *(float2*)(out + row1) = r1;
        }
    }
}

// ---------------------------------------------------------------------------

extern "C" void kernel_launch(void* const* d_in, const int* in_sizes, int n_in,
                              void* d_out, int out_size)
{
    (void)in_sizes; (void)n_in; (void)out_size;
    const float* x     = (const float*)d_in[0];
    const float* Wqkv  = (const float*)d_in[1];
    const float* bqkv  = (const float*)d_in[2];
    const float* Wproj = (const float*)d_in[3];
    const float* bproj = (const float*)d_in[4];
    float* out = (float*)d_out;

    float *qkv_p, *attn_p;
    uint32_t *xt, *wqt, *wpt;
    cudaGetSymbolAddress((void**)&qkv_p, g_qkv);
    cudaGetSymbolAddress((void**)&attn_p, g_attn);
    cudaGetSymbolAddress((void**)&xt, g_xt);
    cudaGetSymbolAddress((void**)&wqt, g_wqt);
    cudaGetSymbolAddress((void**)&wpt, g_wpt);

    cudaFuncSetAttribute(mqa_attn_tf32, cudaFuncAttributeMaxDynamicSharedMemorySize,
                         ATTN_SMEM_BYTES);
    cudaFuncSetAttribute(gemm_tf32ca<true>, cudaFuncAttributeMaxDynamicSharedMemorySize,
                         GEMM_SMEM_BYTES);
    cudaFuncSetAttribute(gemm_tf32ca<false>, cudaFuncAttributeMaxDynamicSharedMemorySize,
                         GEMM_SMEM_BYTES);

    // 0) pre-round + pre-transpose
    round_tf32<<<(MROWS * H / 4 + 255) / 256, 256>>>(x, xt, MROWS * H / 4);
    transpose_round<<<dim3(NQKV / 32, H / 32), 256>>>(Wqkv, wqt, H, NQKV);
    transpose_round<<<dim3(H / 32, H / 32), 256>>>(Wproj, wpt, H, H);

    // 1) QKV GEMM (256x128 tiles, 3-stage cp.async; output tf32-rounded)
    gemm_tf32ca<true><<<dim3(NQKV / 128, MROWS / 256), 512, GEMM_SMEM_BYTES>>>(
        xt, wqt, bqkv, qkv_p, H, NQKV);

    // 2) causal MQA flash attention (async-prefetch TF32)
    mqa_attn_tf32<<<dim3(SEQ / 128, NH, BATCH), 256, ATTN_SMEM_BYTES>>>(qkv_p, attn_p);

    // 3) proj GEMM -> d_out (fp32 output, no rounding)
    gemm_tf32ca<false><<<dim3(H / 128, MROWS / 256), 512, GEMM_SMEM_BYTES>>>(
        (const uint32_t*)attn_p, wpt, bproj, out, H, H);
}